// round 16
// baseline (speedup 1.0000x reference)
#include <cuda_runtime.h>
#include <cuda_bf16.h>

// BoundaryLoss: mean(sigmoid(logits) * EDT2D(target)), [8,1,256,256].
//
// Stage 1 (k_rowdist): warp-per-row exact 1D row distance^2 (shuffle scans)
//   AND sigmoid(logits); both written TRANSPOSED [b][w][i] (i contiguous)
//   through an 8x256 smem tile (coalesced 32B chunks per w).
// Stage 2 (k_edt_loss): thread = 4 consecutive i of one column (float4).
//   Window j in [i-4,i+4] = 3 contiguous float4 loads (prev/own/next, same
//   L1 line region) -> pure register fmin tree. probt float4 load. Rare
//   exact tail scans the contiguous transposed column. Block reduce +
//   one atomicAdd per CTA.

#define B 8
#define H 256
#define W 256
#define NPIX (B * H * W)          // 524288
#define NV4  (NPIX / 4)           // 131072 float4 tasks
#define BIGD 1000000.0f
#define FULL 0xffffffffu

__device__ float g_dr2t[NPIX];    // transposed squared row distances [b][w][i]
__device__ float g_pt[NPIX];      // transposed sigmoid(logits)       [b][w][i]

__global__ __launch_bounds__(256)
void k_rowdist(const int* __restrict__ target,
               const float* __restrict__ logits,
               float* __restrict__ out)
{
    __shared__ float sd[8][256];
    __shared__ float sp[8][256];

    if (blockIdx.x == 0 && threadIdx.x == 0) *out = 0.0f;

    const int tid  = threadIdx.x;
    const int lane = tid & 31;
    const int warp = tid >> 5;
    const int row  = (blockIdx.x << 3) + warp;     // 8 rows per block
    const int base = row * W;
    const int w0   = lane << 3;                    // 8 px per lane

    const int4* tp = reinterpret_cast<const int4*>(target + base + w0);
    const int4 t0 = tp[0];
    const int4 t1 = tp[1];
    int fg[8];
    fg[0] = t0.x > 0; fg[1] = t0.y > 0; fg[2] = t0.z > 0; fg[3] = t0.w > 0;
    fg[4] = t1.x > 0; fg[5] = t1.y > 0; fg[6] = t1.z > 0; fg[7] = t1.w > 0;

    // nearest fg <= w : prefix max of (fg? w : -1)
    int pl[8];
    int run = -1;
#pragma unroll
    for (int k = 0; k < 8; ++k) {
        const int cand = fg[k] ? (w0 + k) : -1;
        run = max(run, cand);
        pl[k] = run;
    }
    int x = run;
#pragma unroll
    for (int off = 1; off < 32; off <<= 1) {
        const int y = __shfl_up_sync(FULL, x, off);
        if (lane >= off) x = max(x, y);
    }
    int exl = __shfl_up_sync(FULL, x, 1);
    if (lane == 0) exl = -1;

    // nearest fg >= w : suffix min of (fg? w : 512)
    int pr[8];
    int run2 = 512;
#pragma unroll
    for (int k = 7; k >= 0; --k) {
        const int cand = fg[k] ? (w0 + k) : 512;
        run2 = min(run2, cand);
        pr[k] = run2;
    }
    int x2 = run2;
#pragma unroll
    for (int off = 1; off < 32; off <<= 1) {
        const int y = __shfl_down_sync(FULL, x2, off);
        if (lane + off < 32) x2 = min(x2, y);
    }
    int exr = __shfl_down_sync(FULL, x2, 1);
    if (lane == 31) exr = 512;

    // row distances^2 -> smem tile
#pragma unroll
    for (int k = 0; k < 8; ++k) {
        const int L = max(pl[k], exl);
        const int R = min(pr[k], exr);
        const float dl = (L >= 0)  ? (float)(w0 + k - L) : BIGD;
        const float dr = (R < 512) ? (float)(R - (w0 + k)) : BIGD;
        const float d  = fminf(dl, dr);
        sd[warp][w0 + k] = d * d;
    }

    // sigmoid(logits) -> smem tile
    {
        const float4 l0 = reinterpret_cast<const float4*>(logits + base + w0)[0];
        const float4 l1 = reinterpret_cast<const float4*>(logits + base + w0)[1];
        sp[warp][w0 + 0] = 1.0f / (1.0f + __expf(-l0.x));
        sp[warp][w0 + 1] = 1.0f / (1.0f + __expf(-l0.y));
        sp[warp][w0 + 2] = 1.0f / (1.0f + __expf(-l0.z));
        sp[warp][w0 + 3] = 1.0f / (1.0f + __expf(-l0.w));
        sp[warp][w0 + 4] = 1.0f / (1.0f + __expf(-l1.x));
        sp[warp][w0 + 5] = 1.0f / (1.0f + __expf(-l1.y));
        sp[warp][w0 + 6] = 1.0f / (1.0f + __expf(-l1.z));
        sp[warp][w0 + 7] = 1.0f / (1.0f + __expf(-l1.w));
    }
    __syncthreads();

    // transposed write-out: thread tid = column w; 8 i-values contiguous
    const int b  = blockIdx.x >> 5;                // image
    const int i0 = (blockIdx.x & 31) << 3;         // first row of this block
    const int w  = tid;
    float vd[8], vp[8];
#pragma unroll
    for (int k = 0; k < 8; ++k) { vd[k] = sd[k][w]; vp[k] = sp[k][w]; }

    float* dst_d = g_dr2t + (b * W + w) * H + i0;
    float* dst_p = g_pt   + (b * W + w) * H + i0;
    reinterpret_cast<float4*>(dst_d)[0] = make_float4(vd[0], vd[1], vd[2], vd[3]);
    reinterpret_cast<float4*>(dst_d)[1] = make_float4(vd[4], vd[5], vd[6], vd[7]);
    reinterpret_cast<float4*>(dst_p)[0] = make_float4(vp[0], vp[1], vp[2], vp[3]);
    reinterpret_cast<float4*>(dst_p)[1] = make_float4(vp[4], vp[5], vp[6], vp[7]);
}

__global__ __launch_bounds__(256)
void k_edt_loss(float* __restrict__ out)
{
    const int v   = blockIdx.x * blockDim.x + threadIdx.x;  // f4 task
    const int i4  = v & 63;                                 // f4 index along i
    // column id cw = b*W + w is v >> 6; linear f4 base = v itself.

    const float4* dt = reinterpret_cast<const float4*>(g_dr2t);
    const float4* pt = reinterpret_cast<const float4*>(g_pt);
    const float4  big = make_float4(BIGD, BIGD, BIGD, BIGD);

    // 12 contiguous window values: j in [4*i4-4, 4*i4+7]
    const float4 ow = dt[v];
    const float4 pv4 = pt[v];
    const float4 pw4 = (i4 > 0)  ? dt[v - 1] : big;
    const float4 nx4 = (i4 < 63) ? dt[v + 1] : big;

    float buf[12];
    buf[0] = pw4.x; buf[1] = pw4.y; buf[2]  = pw4.z; buf[3]  = pw4.w;
    buf[4] = ow.x;  buf[5] = ow.y;  buf[6]  = ow.z;  buf[7]  = ow.w;
    buf[8] = nx4.x; buf[9] = nx4.y; buf[10] = nx4.z; buf[11] = nx4.w;

    float cur[4];
#pragma unroll
    for (int k = 0; k < 4; ++k) {
        float c = buf[k + 4];                      // j = i
#pragma unroll
        for (int r = 1; r <= 4; ++r) {
            const float rr = (float)(r * r);
            c = fminf(c, fminf(buf[k + 4 - r], buf[k + 4 + r]) + rr);
        }
        cur[k] = c;
    }

    // rare exact tail: r >= 5, contiguous transposed column scan
    if (fmaxf(fmaxf(cur[0], cur[1]), fmaxf(cur[2], cur[3])) > 25.0f) {
        const float* dcol = g_dr2t + (v >> 6) * H;  // this column, i contiguous
#pragma unroll
        for (int k = 0; k < 4; ++k) {
            const int i = (i4 << 2) + k;
            for (int r = 5; r < H && (float)(r * r) < cur[k]; ++r) {
                const float rr = (float)(r * r);
                if (i >= r)    cur[k] = fminf(cur[k], dcol[i - r] + rr);
                if (i + r < H) cur[k] = fminf(cur[k], dcol[i + r] + rr);
            }
        }
    }

    float val = pv4.x * sqrtf(cur[0]) + pv4.y * sqrtf(cur[1])
              + pv4.z * sqrtf(cur[2]) + pv4.w * sqrtf(cur[3]);
    val *= (1.0f / (float)NPIX);

    // block reduction -> one atomic per CTA
#pragma unroll
    for (int o = 16; o; o >>= 1)
        val += __shfl_xor_sync(FULL, val, o);

    __shared__ float ws[8];
    if ((threadIdx.x & 31) == 0) ws[threadIdx.x >> 5] = val;
    __syncthreads();
    if (threadIdx.x == 0) {
        float t = ws[0];
#pragma unroll
        for (int k = 1; k < 8; ++k) t += ws[k];
        atomicAdd(out, t);
    }
}

extern "C" void kernel_launch(void* const* d_in, const int* in_sizes, int n_in,
                              void* d_out, int out_size)
{
    const float* logits = (const float*)d_in[0];
    const int*   target = (const int*)d_in[1];
    float*       out    = (float*)d_out;

    k_rowdist<<<(B * H) / 8, 256>>>(target, logits, out);
    k_edt_loss<<<NV4 / 256, 256>>>(out);
}

// round 17
// speedup vs baseline: 1.0239x; 1.0239x over previous
#include <cuda_runtime.h>
#include <cuda_bf16.h>

// BoundaryLoss: mean(sigmoid(logits) * EDT2D(target)), [8,1,256,256].
//
// SINGLE fused kernel, 512 CTAs x 256 thr, __launch_bounds__(256,4) =>
// all CTAs co-resident (592 slots) => grid barrier deadlock-free.
//   Phase 1: CTA c scans its 4 rows (warps 0..3, shuffle scans) -> global
//            g_dr2 AND a 4KB smem tile. Release __threadfence() only in
//            the 4 writer warps. Logits prefetched by all threads.
//   Barrier: monotonic-epoch counter + __nanosleep spin (replay-safe).
//            NO acquire fence: phase-2 dr2 global reads use __ldcg
//            (L2-direct), so L1 staleness cannot occur.
//   Phase 2: float4 window min, j in [i-4,i+4]; in-tile rows from smem
//            (warp-uniform branch), halo rows via __ldcg (~4.5/thread).
//            Rare exact tail via __ldcg. Block reduce + 1 atomicAdd.

#define B 8
#define H 256
#define W 256
#define NPIX (B * H * W)          // 524288
#define BIGD 1000000.0f
#define FULL 0xffffffffu
#define RW4 (W / 4)               // 64 float4 per row
#define NCTA 512

__device__ float    g_dr2[NPIX];
__device__ unsigned g_bar = 0u;   // monotonic across graph replays

__device__ __forceinline__ float4 fmin4a(float4 a, float4 bu, float4 bd, float rr)
{
    a.x = fminf(a.x, fminf(bu.x, bd.x) + rr);
    a.y = fminf(a.y, fminf(bu.y, bd.y) + rr);
    a.z = fminf(a.z, fminf(bu.z, bd.z) + rr);
    a.w = fminf(a.w, fminf(bu.w, bd.w) + rr);
    return a;
}

__global__ __launch_bounds__(256, 4)
void k_fused(const float* __restrict__ logits,
             const int* __restrict__ target,
             float* __restrict__ out)
{
    __shared__ float sd[4][W];    // this CTA's 4 dr2 rows
    __shared__ float ws[8];

    const int tid  = threadIdx.x;
    const int lane = tid & 31;
    const int warp = tid >> 5;
    const int c    = blockIdx.x;
    const int b    = c >> 6;      // image

    // prefetch phase-2 logits (overlaps scan + barrier)
    const int v = c * 256 + tid;  // this thread's float4 task
    const float4 xv = reinterpret_cast<const float4*>(logits)[v];

    if (c == 0 && tid == 0) *out = 0.0f;   // ordered by writer-warp fence

    // ================= Phase 1: row distances (warps 0..3) =================
    if (warp < 4) {
        const int row  = (c << 2) + warp;          // global row 0..2047
        const int base = row * W;
        const int w0   = lane << 3;                // 8 px per lane

        const int4* tp = reinterpret_cast<const int4*>(target + base + w0);
        const int4 t0 = tp[0];
        const int4 t1 = tp[1];
        int fg[8];
        fg[0] = t0.x > 0; fg[1] = t0.y > 0; fg[2] = t0.z > 0; fg[3] = t0.w > 0;
        fg[4] = t1.x > 0; fg[5] = t1.y > 0; fg[6] = t1.z > 0; fg[7] = t1.w > 0;

        // nearest fg <= w : prefix max of (fg? w : -1)
        int pl[8];
        int run = -1;
#pragma unroll
        for (int k = 0; k < 8; ++k) {
            const int cand = fg[k] ? (w0 + k) : -1;
            run = max(run, cand);
            pl[k] = run;
        }
        int x = run;
#pragma unroll
        for (int off = 1; off < 32; off <<= 1) {
            const int y = __shfl_up_sync(FULL, x, off);
            if (lane >= off) x = max(x, y);
        }
        int exl = __shfl_up_sync(FULL, x, 1);
        if (lane == 0) exl = -1;

        // nearest fg >= w : suffix min of (fg? w : 512)
        int pr[8];
        int run2 = 512;
#pragma unroll
        for (int k = 7; k >= 0; --k) {
            const int cand = fg[k] ? (w0 + k) : 512;
            run2 = min(run2, cand);
            pr[k] = run2;
        }
        int x2 = run2;
#pragma unroll
        for (int off = 1; off < 32; off <<= 1) {
            const int y = __shfl_down_sync(FULL, x2, off);
            if (lane + off < 32) x2 = min(x2, y);
        }
        int exr = __shfl_down_sync(FULL, x2, 1);
        if (lane == 31) exr = 512;

        float o[8];
#pragma unroll
        for (int k = 0; k < 8; ++k) {
            const int L = max(pl[k], exl);
            const int R = min(pr[k], exr);
            const float dl = (L >= 0)  ? (float)(w0 + k - L) : BIGD;
            const float dr = (R < 512) ? (float)(R - (w0 + k)) : BIGD;
            const float d  = fminf(dl, dr);
            o[k] = d * d;
            sd[warp][w0 + k] = o[k];               // local copy for phase 2
        }
        float4* op = reinterpret_cast<float4*>(g_dr2 + base + w0);
        op[0] = make_float4(o[0], o[1], o[2], o[3]);
        op[1] = make_float4(o[4], o[5], o[6], o[7]);

        __threadfence();   // release: this warp's dr2 stores -> L2 (writers only)
    }

    // ================= Grid barrier (epoch, replay-safe, no acquire) =======
    __syncthreads();
    if (tid == 0) {
        const unsigned prev = atomicAdd(&g_bar, 1u);
        const unsigned tgt  = (prev / NCTA + 1u) * NCTA;
        while (*(volatile unsigned*)&g_bar < tgt) __nanosleep(64);
    }
    __syncthreads();

    // ================= Phase 2: column EDT + loss =================
    const int lr = tid >> 6;                   // row within tile 0..3
    const int cf = tid & 63;                   // float4 column
    const int il = ((c & 63) << 2) + lr;       // row within image

    const float4* gd4 = reinterpret_cast<const float4*>(g_dr2);
    const float4* sd4 = reinterpret_cast<const float4*>(sd);
    const float4  big = make_float4(BIGD, BIGD, BIGD, BIGD);

    float4 cur = sd4[lr * 64 + cf];            // j = i (own smem row)
#pragma unroll
    for (int r = 1; r <= 4; ++r) {
        const float rr = (float)(r * r);
        float4 vu, vd;
        if (lr >= r) {                         // warp-uniform branch
            vu = sd4[(lr - r) * 64 + cf];
        } else {
            const int j = il - r;
            vu = (j >= 0) ? __ldcg(&gd4[(b * H + j) * RW4 + cf]) : big;
        }
        if (lr + r <= 3) {
            vd = sd4[(lr + r) * 64 + cf];
        } else {
            const int j = il + r;
            vd = (j < H) ? __ldcg(&gd4[(b * H + j) * RW4 + cf]) : big;
        }
        cur = fmin4a(cur, vu, vd, rr);
    }

    // rare exact tail: r >= 5, scalar per component via __ldcg
    if (fmaxf(fmaxf(cur.x, cur.y), fmaxf(cur.z, cur.w)) > 25.0f) {
        float* cc = &cur.x;
        const int p0 = (b * H + il) * W + cf * 4;
#pragma unroll
        for (int q = 0; q < 4; ++q) {
            for (int r = 5; r < H && (float)(r * r) < cc[q]; ++r) {
                const float rr = (float)(r * r);
                if (il >= r)
                    cc[q] = fminf(cc[q], __ldcg(&g_dr2[p0 + q - (r << 8)]) + rr);
                if (il + r < H)
                    cc[q] = fminf(cc[q], __ldcg(&g_dr2[p0 + q + (r << 8)]) + rr);
            }
        }
    }

    const float px = 1.0f / (1.0f + __expf(-xv.x));
    const float py = 1.0f / (1.0f + __expf(-xv.y));
    const float pz = 1.0f / (1.0f + __expf(-xv.z));
    const float pw = 1.0f / (1.0f + __expf(-xv.w));

    float val = px * sqrtf(cur.x) + py * sqrtf(cur.y)
              + pz * sqrtf(cur.z) + pw * sqrtf(cur.w);
    val *= (1.0f / (float)NPIX);

    // block reduction -> one atomic per CTA
#pragma unroll
    for (int o = 16; o; o >>= 1)
        val += __shfl_xor_sync(FULL, val, o);

    if (lane == 0) ws[warp] = val;
    __syncthreads();
    if (tid == 0) {
        float t = ws[0];
#pragma unroll
        for (int k = 1; k < 8; ++k) t += ws[k];
        atomicAdd(out, t);
    }
}

extern "C" void kernel_launch(void* const* d_in, const int* in_sizes, int n_in,
                              void* d_out, int out_size)
{
    const float* logits = (const float*)d_in[0];
    const int*   target = (const int*)d_in[1];
    float*       out    = (float*)d_out;

    k_fused<<<NCTA, 256>>>(logits, target, out);
}